// round 3
// baseline (speedup 1.0000x reference)
#include <cuda_runtime.h>
#include <cuda_bf16.h>
#include <cstdint>

#define N_NODES 100000
#define N_EDGES 800000
#define H 128

#define TILE_M 128
#define THREADS 512
#define HPITCH 128   // h tile pitch (a reads broadcast 2 addr/warp; float4 aligned)
#define WPITCH 132   // transposed W tile pitch (multiple of 4 for LDS.128)
#define SMEM_FLOATS (TILE_M * HPITCH + 2 * H * WPITCH)
#define SMEM_BYTES (SMEM_FLOATS * 4)

// Scratch for Wh (forward message transform) and Wth (backward message transform)
__device__ float g_Wh[(size_t)N_NODES * H];
__device__ float g_Wth[(size_t)N_NODES * H];

__device__ __forceinline__ unsigned long long pack2(float lo, float hi) {
    unsigned long long r;
    asm("mov.b64 %0, {%1, %2};" : "=l"(r) : "f"(lo), "f"(hi));
    return r;
}
__device__ __forceinline__ void unpack2(unsigned long long v, float& lo, float& hi) {
    asm("mov.b64 {%0, %1}, %2;" : "=f"(lo), "=f"(hi) : "l"(v));
}
__device__ __forceinline__ void fma2(unsigned long long& acc,
                                     unsigned long long a, unsigned long long b) {
    asm("fma.rn.f32x2 %0, %1, %2, %3;" : "=l"(acc) : "l"(a), "l"(b), "l"(acc));
}
__device__ __forceinline__ void red4(float* p, float4 v) {
    asm volatile("red.global.add.v4.f32 [%0], {%1, %2, %3, %4};"
                 :: "l"(p), "f"(v.x), "f"(v.y), "f"(v.z), "f"(v.w) : "memory");
}

// For a 128-row tile of h:
//   w=0: g_Wh  = h @ W_w^T  + W_b
//   w=1: d_out = h @ Ws_w^T + Ws_b   (initializes the accumulation buffer)
//   w=2: g_Wth = h @ Wt_w^T + Wt_b
// W tiles double-buffered; stage of W_{w+1} overlaps compute of W_w.
__global__ __launch_bounds__(THREADS, 1)
void gemm3_kernel(const float* __restrict__ h,
                  const float* __restrict__ W0, const float* __restrict__ b0,
                  const float* __restrict__ W1, const float* __restrict__ b1,
                  const float* __restrict__ W2, const float* __restrict__ b2,
                  float* __restrict__ out_self) {
    extern __shared__ float smem[];
    float* hs  = smem;                                 // [TILE_M][HPITCH]
    float* WbA = smem + TILE_M * HPITCH;               // [H(k)][WPITCH]
    float* WbB = WbA + H * WPITCH;

    const int tid = threadIdx.x;
    const int tx = tid & 15;     // col group: cols 4*tx+64*j+{0..3}
    const int ty = tid >> 4;     // row group: rows ty+32*i, i=0..3
    const int rowBase = blockIdx.x * TILE_M;

    const float* Wg[3] = {W0, W1, W2};
    const float* bg[3] = {b0, b1, b2};

    // ---- stage h tile (coalesced float4) ----
    #pragma unroll
    for (int it = 0; it < 8; ++it) {
        int idx = tid + it * THREADS;      // 0..4095 (128 rows x 32 float4)
        int r  = idx >> 5;
        int k4 = idx & 31;
        float4 v = make_float4(0.f, 0.f, 0.f, 0.f);
        int gr = rowBase + r;
        if (gr < N_NODES)
            v = *(const float4*)(h + (size_t)gr * H + k4 * 4);
        *(float4*)(hs + r * HPITCH + k4 * 4) = v;
    }

    // ---- stage W0 into buffer A (transposed: Wst[k][o] = W[o][k]) ----
    #pragma unroll
    for (int it = 0; it < 8; ++it) {
        int idx = tid + it * THREADS;
        int o  = idx >> 5;
        int k4 = idx & 31;
        float4 v = *(const float4*)(W0 + o * H + k4 * 4);
        WbA[(k4 * 4 + 0) * WPITCH + o] = v.x;
        WbA[(k4 * 4 + 1) * WPITCH + o] = v.y;
        WbA[(k4 * 4 + 2) * WPITCH + o] = v.z;
        WbA[(k4 * 4 + 3) * WPITCH + o] = v.w;
    }
    __syncthreads();

    #pragma unroll
    for (int w = 0; w < 3; ++w) {
        float* Wcur  = (w & 1) ? WbB : WbA;
        float* Wnext = (w & 1) ? WbA : WbB;
        const float* bias = bg[w];
        float* dst = (w == 0) ? g_Wh : (w == 1) ? out_self : g_Wth;

        // ---- prefetch next W into other buffer (overlaps compute) ----
        if (w < 2) {
            const float* W = Wg[w + 1];
            #pragma unroll
            for (int it = 0; it < 8; ++it) {
                int idx = tid + it * THREADS;
                int o  = idx >> 5;
                int k4 = idx & 31;
                float4 v = *(const float4*)(W + o * H + k4 * 4);
                Wnext[(k4 * 4 + 0) * WPITCH + o] = v.x;
                Wnext[(k4 * 4 + 1) * WPITCH + o] = v.y;
                Wnext[(k4 * 4 + 2) * WPITCH + o] = v.z;
                Wnext[(k4 * 4 + 3) * WPITCH + o] = v.w;
            }
        }

        // ---- compute: acc[i][p] = col pair (4tx+64j+2q, +1), p=2j+q ----
        unsigned long long acc[4][4];
        #pragma unroll
        for (int i = 0; i < 4; ++i)
            #pragma unroll
            for (int p = 0; p < 4; ++p) acc[i][p] = 0ULL;

        #pragma unroll 2
        for (int k0 = 0; k0 < H; k0 += 4) {
            float4 a4[4];
            #pragma unroll
            for (int i = 0; i < 4; ++i)
                a4[i] = *(const float4*)(hs + (ty + 32 * i) * HPITCH + k0);

            #pragma unroll
            for (int kk = 0; kk < 4; ++kk) {
                const float* wr = Wcur + (k0 + kk) * WPITCH + 4 * tx;
                float4 bv0 = *(const float4*)(wr);
                float4 bv1 = *(const float4*)(wr + 64);
                unsigned long long bp[4] = {
                    pack2(bv0.x, bv0.y), pack2(bv0.z, bv0.w),
                    pack2(bv1.x, bv1.y), pack2(bv1.z, bv1.w)
                };
                #pragma unroll
                for (int i = 0; i < 4; ++i) {
                    float av = (kk == 0) ? a4[i].x : (kk == 1) ? a4[i].y
                             : (kk == 2) ? a4[i].z : a4[i].w;
                    unsigned long long a2 = pack2(av, av);
                    #pragma unroll
                    for (int p = 0; p < 4; ++p) fma2(acc[i][p], a2, bp[p]);
                }
            }
        }

        // ---- epilogue: add bias, coalesced float4 stores ----
        float4 bias4[2];
        bias4[0] = *(const float4*)(bias + 4 * tx);
        bias4[1] = *(const float4*)(bias + 4 * tx + 64);
        #pragma unroll
        for (int i = 0; i < 4; ++i) {
            int row = rowBase + ty + 32 * i;
            if (row < N_NODES) {
                float* drow = dst + (size_t)row * H + 4 * tx;
                #pragma unroll
                for (int j = 0; j < 2; ++j) {
                    float4 o;
                    unpack2(acc[i][2 * j],     o.x, o.y);
                    unpack2(acc[i][2 * j + 1], o.z, o.w);
                    o.x += bias4[j].x; o.y += bias4[j].y;
                    o.z += bias4[j].z; o.w += bias4[j].w;
                    *(float4*)(drow + 64 * j) = o;
                }
            }
        }
        __syncthreads();
    }
}

// One warp per edge; both aggregation directions; 16B vector reduces.
// out[src] += Wh[dst];  out[dst] += Wth[src];
__global__ __launch_bounds__(256)
void scatter_kernel(const int* __restrict__ esrc, const int* __restrict__ edst,
                    float* __restrict__ out) {
    int warp = (blockIdx.x * blockDim.x + threadIdx.x) >> 5;
    int lane = threadIdx.x & 31;
    if (warp >= N_EDGES) return;
    int s = __ldg(esrc + warp);
    int d = __ldg(edst + warp);

    const float4 vf = *(const float4*)(g_Wh  + (size_t)d * H + lane * 4);
    const float4 vb = *(const float4*)(g_Wth + (size_t)s * H + lane * 4);

    red4(out + (size_t)s * H + lane * 4, vf);
    red4(out + (size_t)d * H + lane * 4, vb);
}

__global__ __launch_bounds__(256)
void relu_kernel(float* __restrict__ out) {
    int i = blockIdx.x * blockDim.x + threadIdx.x;
    const int total4 = (N_NODES * H) / 4;
    if (i < total4) {
        float4 v = ((float4*)out)[i];
        v.x = fmaxf(v.x, 0.f);
        v.y = fmaxf(v.y, 0.f);
        v.z = fmaxf(v.z, 0.f);
        v.w = fmaxf(v.w, 0.f);
        ((float4*)out)[i] = v;
    }
}

extern "C" void kernel_launch(void* const* d_in, const int* in_sizes, int n_in,
                              void* d_out, int out_size) {
    const float* h_n   = (const float*)d_in[0];
    const int*   esrc  = (const int*)d_in[1];
    const int*   edst  = (const int*)d_in[2];
    const float* W_w   = (const float*)d_in[3];
    const float* W_b   = (const float*)d_in[4];
    const float* Ws_w  = (const float*)d_in[5];
    const float* Ws_b  = (const float*)d_in[6];
    const float* Wt_w  = (const float*)d_in[7];
    const float* Wt_b  = (const float*)d_in[8];
    float* out = (float*)d_out;

    cudaFuncSetAttribute(gemm3_kernel,
                         cudaFuncAttributeMaxDynamicSharedMemorySize, SMEM_BYTES);

    int gemm_blocks = (N_NODES + TILE_M - 1) / TILE_M;   // 782
    gemm3_kernel<<<gemm_blocks, THREADS, SMEM_BYTES>>>(
        h_n, W_w, W_b, Ws_w, Ws_b, Wt_w, Wt_b, out);

    int scatter_blocks = (N_EDGES * 32 + 255) / 256;     // 100000
    scatter_kernel<<<scatter_blocks, 256>>>(esrc, edst, out);

    int relu_blocks = ((N_NODES * H) / 4 + 255) / 256;
    relu_kernel<<<relu_blocks, 256>>>(out);
}

// round 5
// speedup vs baseline: 1.5672x; 1.5672x over previous
#include <cuda_runtime.h>
#include <cuda_bf16.h>
#include <cstdint>

#define N_NODES 100000
#define N_EDGES 800000
#define H 128

#define THREADS 256
#define TILE_M 128
#define KPITCH 136                    // bf16 elems per smem row (272 B, bank-spread)
#define TILEB (128 * KPITCH * 2)      // 34816 B per 128x128 bf16 tile

#define SM_BIAS 0                     // 3*128 floats
#define SM_A_HI 2048
#define SM_A_LO (SM_A_HI + TILEB)
#define SM_W_HI(b) (SM_A_LO + TILEB + (b) * 2 * TILEB)
#define SM_W_LO(b) (SM_W_HI(b) + TILEB)
#define SMEM_BYTES (SM_W_LO(1) + TILEB)   // 210944 B

__device__ float g_Wh[(size_t)N_NODES * H];
__device__ float g_Wth[(size_t)N_NODES * H];

__device__ __forceinline__ uint32_t smem_u32(const void* p) {
    uint32_t a;
    asm("{ .reg .u64 t; cvta.to.shared.u64 t, %1; cvt.u32.u64 %0, t; }" : "=r"(a) : "l"(p));
    return a;
}
__device__ __forceinline__ void ldsm4(uint32_t* r, uint32_t addr) {
    asm volatile("ldmatrix.sync.aligned.m8n8.x4.shared.b16 {%0,%1,%2,%3}, [%4];"
                 : "=r"(r[0]), "=r"(r[1]), "=r"(r[2]), "=r"(r[3]) : "r"(addr));
}
__device__ __forceinline__ void mma_bf16(float* c, const uint32_t* a, const uint32_t* b) {
    asm volatile(
        "mma.sync.aligned.m16n8k16.row.col.f32.bf16.bf16.f32 "
        "{%0,%1,%2,%3}, {%4,%5,%6,%7}, {%8,%9}, {%0,%1,%2,%3};"
        : "+f"(c[0]), "+f"(c[1]), "+f"(c[2]), "+f"(c[3])
        : "r"(a[0]), "r"(a[1]), "r"(a[2]), "r"(a[3]), "r"(b[0]), "r"(b[1]));
}
__device__ __forceinline__ void red4(float* p, float4 v) {
    asm volatile("red.global.add.v4.f32 [%0], {%1, %2, %3, %4};"
                 :: "l"(p), "f"(v.x), "f"(v.y), "f"(v.z), "f"(v.w) : "memory");
}
__device__ __forceinline__ uint32_t pack_bf2(__nv_bfloat16 a, __nv_bfloat16 b) {
    return ((uint32_t)__bfloat16_as_ushort(b) << 16) | __bfloat16_as_ushort(a);
}
// Split float4 (row, c0..c0+3) into hi/lo bf16 and store to pitched smem tiles.
__device__ __forceinline__ void stage4(char* smem, uint32_t hi_off, uint32_t lo_off,
                                       int row, int c0, float4 v) {
    __nv_bfloat16 h0 = __float2bfloat16(v.x), h1 = __float2bfloat16(v.y);
    __nv_bfloat16 h2 = __float2bfloat16(v.z), h3 = __float2bfloat16(v.w);
    __nv_bfloat16 l0 = __float2bfloat16(v.x - __bfloat162float(h0));
    __nv_bfloat16 l1 = __float2bfloat16(v.y - __bfloat162float(h1));
    __nv_bfloat16 l2 = __float2bfloat16(v.z - __bfloat162float(h2));
    __nv_bfloat16 l3 = __float2bfloat16(v.w - __bfloat162float(h3));
    uint32_t t = (uint32_t)(row * KPITCH + c0) * 2;       // 8B aligned (c0 % 4 == 0)
    *(uint2*)(smem + hi_off + t) = make_uint2(pack_bf2(h0, h1), pack_bf2(h2, h3));
    *(uint2*)(smem + lo_off + t) = make_uint2(pack_bf2(l0, l1), pack_bf2(l2, l3));
}

// For a 128-row tile of h, computes D_w = h @ W_w^T + b_w (3xBF16 split MMA).
// w=0 -> g_Wh, w=1 -> d_out (initializes accumulation buffer), w=2 -> g_Wth
__global__ __launch_bounds__(THREADS, 1)
void gemm3_mma(const float* __restrict__ h,
               const float* __restrict__ W0, const float* __restrict__ b0,
               const float* __restrict__ W1, const float* __restrict__ b1,
               const float* __restrict__ W2, const float* __restrict__ b2,
               float* __restrict__ out_self) {
    extern __shared__ char smem[];
    const uint32_t sbase = smem_u32(smem);
    const int tid = threadIdx.x;
    const int lane = tid & 31;
    const int wid = tid >> 5;
    const int rowBase = blockIdx.x * TILE_M;

    const float* Wg[3] = {W0, W1, W2};
    const float* bg[3] = {b0, b1, b2};

    // bias -> smem
    if (tid < 384 / 2) { // 192 threads won't cover; use loop instead
    }
    for (int i = tid; i < 384; i += THREADS)
        *(float*)(smem + SM_BIAS + i * 4) = bg[i >> 7][i & 127];

    // ---- stage A (h tile, hi/lo): 128 rows x 32 float4 ----
    #pragma unroll
    for (int it = 0; it < 16; ++it) {
        int idx = tid + it * THREADS;
        int r = idx >> 5, k4 = idx & 31;
        float4 v = make_float4(0.f, 0.f, 0.f, 0.f);
        int gr = rowBase + r;
        if (gr < N_NODES) v = *(const float4*)(h + (size_t)gr * H + k4 * 4);
        stage4(smem, SM_A_HI, SM_A_LO, r, k4 * 4, v);
    }
    // ---- stage W0 into buffer 0 ----
    #pragma unroll
    for (int it = 0; it < 16; ++it) {
        int idx = tid + it * THREADS;
        int o = idx >> 5, k4 = idx & 31;
        float4 v = *(const float4*)(W0 + o * H + k4 * 4);
        stage4(smem, SM_W_HI(0), SM_W_LO(0), o, k4 * 4, v);
    }
    __syncthreads();

    const int m0 = (wid & 3) * 32;    // warp's 32 output rows
    const int n0 = (wid >> 2) * 64;   // warp's 64 output cols
    // ldmatrix per-lane byte offsets
    const uint32_t aoff = (uint32_t)(((lane & 7) + ((lane >> 3) & 1) * 8) * KPITCH
                                     + (lane >> 4) * 8) * 2;
    const uint32_t boff = (uint32_t)(((lane & 7) + ((lane >> 4) & 1) * 8) * KPITCH
                                     + ((lane >> 3) & 1) * 8) * 2;

    #pragma unroll
    for (int w = 0; w < 3; ++w) {
        const int buf = w & 1;
        // stage next W into the other buffer (LDGs overlap MMA issue below)
        if (w < 2) {
            const float* W = Wg[w + 1];
            const int nb = buf ^ 1;
            #pragma unroll
            for (int it = 0; it < 16; ++it) {
                int idx = tid + it * THREADS;
                int o = idx >> 5, k4 = idx & 31;
                float4 v = *(const float4*)(W + o * H + k4 * 4);
                stage4(smem, SM_W_HI(nb), SM_W_LO(nb), o, k4 * 4, v);
            }
        }

        float acc[2][8][4];
        #pragma unroll
        for (int i = 0; i < 2; ++i)
            #pragma unroll
            for (int j = 0; j < 8; ++j)
                #pragma unroll
                for (int q = 0; q < 4; ++q) acc[i][j][q] = 0.f;

        const uint32_t Abase[3] = {sbase + SM_A_HI, sbase + SM_A_HI, sbase + SM_A_LO};
        const uint32_t Bbase[3] = {sbase + (uint32_t)SM_W_HI(buf),
                                   sbase + (uint32_t)SM_W_LO(buf),
                                   sbase + (uint32_t)SM_W_HI(buf)};
        #pragma unroll
        for (int p = 0; p < 3; ++p) {
            const uint32_t Ab = Abase[p] + aoff;
            const uint32_t Bb = Bbase[p] + boff;
            #pragma unroll
            for (int ks = 0; ks < 8; ++ks) {
                const int k = ks * 16;
                uint32_t a[2][4];
                ldsm4(a[0], Ab + (uint32_t)((m0)      * KPITCH + k) * 2);
                ldsm4(a[1], Ab + (uint32_t)((m0 + 16) * KPITCH + k) * 2);
                uint32_t b[4][4];
                #pragma unroll
                for (int j2 = 0; j2 < 4; ++j2)
                    ldsm4(b[j2], Bb + (uint32_t)((n0 + 16 * j2) * KPITCH + k) * 2);
                #pragma unroll
                for (int i = 0; i < 2; ++i)
                    #pragma unroll
                    for (int j = 0; j < 8; ++j)
                        mma_bf16(acc[i][j], a[i], &b[j >> 1][(j & 1) * 2]);
            }
        }

        // ---- epilogue: bias add + float2 stores ----
        float* dst = (w == 0) ? g_Wh : (w == 1) ? out_self : g_Wth;
        const float* bsm = (const float*)(smem + SM_BIAS) + w * 128;
        #pragma unroll
        for (int i = 0; i < 2; ++i) {
            int r0 = rowBase + m0 + 16 * i + (lane >> 2);
            #pragma unroll
            for (int j = 0; j < 8; ++j) {
                int col = n0 + 8 * j + (lane & 3) * 2;
                float bv0 = bsm[col], bv1 = bsm[col + 1];
                if (r0 < N_NODES) {
                    float2 o = make_float2(acc[i][j][0] + bv0, acc[i][j][1] + bv1);
                    *(float2*)(dst + (size_t)r0 * H + col) = o;
                }
                if (r0 + 8 < N_NODES) {
                    float2 o = make_float2(acc[i][j][2] + bv0, acc[i][j][3] + bv1);
                    *(float2*)(dst + (size_t)(r0 + 8) * H + col) = o;
                }
            }
        }
        __syncthreads();
    }
}

// One warp per edge; both aggregation directions; 16B vector reduces.
__global__ __launch_bounds__(256)
void scatter_kernel(const int* __restrict__ esrc, const int* __restrict__ edst,
                    float* __restrict__ out) {
    int warp = (blockIdx.x * blockDim.x + threadIdx.x) >> 5;
    int lane = threadIdx.x & 31;
    if (warp >= N_EDGES) return;
    int s = __ldg(esrc + warp);
    int d = __ldg(edst + warp);

    const float4 vf = *(const float4*)(g_Wh  + (size_t)d * H + lane * 4);
    const float4 vb = *(const float4*)(g_Wth + (size_t)s * H + lane * 4);

    red4(out + (size_t)s * H + lane * 4, vf);
    red4(out + (size_t)d * H + lane * 4, vb);
}

__global__ __launch_bounds__(256)
void relu_kernel(float* __restrict__ out) {
    int i = blockIdx.x * blockDim.x + threadIdx.x;
    const int total4 = (N_NODES * H) / 4;
    if (i < total4) {
        float4 v = ((float4*)out)[i];
        v.x = fmaxf(v.x, 0.f);
        v.y = fmaxf(v.y, 0.f);
        v.z = fmaxf(v.z, 0.f);
        v.w = fmaxf(v.w, 0.f);
        ((float4*)out)[i] = v;
    }
}

extern "C" void kernel_launch(void* const* d_in, const int* in_sizes, int n_in,
                              void* d_out, int out_size) {
    const float* h_n  = (const float*)d_in[0];
    const int*   esrc = (const int*)d_in[1];
    const int*   edst = (const int*)d_in[2];
    const float* W_w  = (const float*)d_in[3];
    const float* W_b  = (const float*)d_in[4];
    const float* Ws_w = (const float*)d_in[5];
    const float* Ws_b = (const float*)d_in[6];
    const float* Wt_w = (const float*)d_in[7];
    const float* Wt_b = (const float*)d_in[8];
    float* out = (float*)d_out;

    cudaFuncSetAttribute(gemm3_mma,
                         cudaFuncAttributeMaxDynamicSharedMemorySize, SMEM_BYTES);

    int gemm_blocks = (N_NODES + TILE_M - 1) / TILE_M;   // 782
    gemm3_mma<<<gemm_blocks, THREADS, SMEM_BYTES>>>(
        h_n, W_w, W_b, Ws_w, Ws_b, Wt_w, Wt_b, out);

    int scatter_blocks = (N_EDGES * 32 + 255) / 256;     // 100000
    scatter_kernel<<<scatter_blocks, 256>>>(esrc, edst, out);

    int relu_blocks = ((N_NODES * H) / 4 + 255) / 256;
    relu_kernel<<<relu_blocks, 256>>>(out);
}